// round 4
// baseline (speedup 1.0000x reference)
#include <cuda_runtime.h>
#include <math.h>
#include <stdint.h>

// Problem constants
#define B_   8
#define N_   512
#define D_   256
#define R_   6
#define BN_  (B_*N_)          // 4096 rows
#define KA_  1552             // 6*256 relation cols + 6 count cols + 10 zero pad (multiple of 16)

// Output layout in d_out (floats):
//   [0, 1048576)            output  [B,N,D]
//   [1048576, +4096)        exoteric [B,N,1]
//   [1052672, +4096)        esoteric
//   [1056768, +4096)        sacred
//   [1060864, +1048576)     symbols [B,N,D]
#define OFF_INTERP 1048576
#define OFF_SYM    (1048576 + 3*4096)

// ---------------- scratch (device globals; no allocations allowed) ----------------
__device__ float g_S0[BN_ * D_];            // embedded symbols
__device__ float g_A[BN_ * KA_];            // grammar GEMM LHS (per-relation sums + counts)
__device__ float g_Wfull[KA_ * D_];         // rel_W stacked + rel_b rows + zero pad
__device__ float g_H[BN_ * 3 * D_];         // head hidden activations (post-GELU)
__device__ float g_P[B_ * (N_ + 1) * D_];   // prefix sums of S0 in y-sorted order
__device__ float g_ysort[B_ * N_];
__device__ int   g_sidx[B_ * N_];
__device__ int   g_k0[B_ * N_];             // band range per sorted position
__device__ int   g_k1[B_ * N_];

// ---------------- kernels ----------------

// symbols0 = sym_table[id] + layer_table[id]
__global__ void k_embed(const int* __restrict__ ids,
                        const float* __restrict__ symt,
                        const float* __restrict__ layt) {
    int row = blockIdx.x;          // 0..4095
    int t   = threadIdx.x;         // 0..255
    int id  = ids[row];
    g_S0[row * D_ + t] = symt[id * D_ + t] + layt[id * D_ + t];
}

// per-batch bitonic sort of y, plus band-range binary searches
__global__ void k_sort(const float* __restrict__ pos) {
    __shared__ float key[N_];
    __shared__ int   val[N_];
    int b = blockIdx.x, t = threadIdx.x;   // 512 threads
    key[t] = pos[(b * N_ + t) * 2 + 1];
    val[t] = t;
    __syncthreads();
    for (int size = 2; size <= N_; size <<= 1) {
        for (int stride = size >> 1; stride > 0; stride >>= 1) {
            int j = t ^ stride;
            if (j > t) {
                bool up = ((t & size) == 0);
                float kt = key[t], kj = key[j];
                if ((kt > kj) == up) {
                    key[t] = kj; key[j] = kt;
                    int vt = val[t]; val[t] = val[j]; val[j] = vt;
                }
            }
            __syncthreads();
        }
    }
    g_ysort[b * N_ + t] = key[t];
    g_sidx[b * N_ + t]  = val[t];
    // band bounds for the element at sorted position t
    float y  = key[t];
    float v0 = y - 0.5f, v1 = y + 0.5f;
    int lo = 0, hi = N_;
    while (lo < hi) { int m = (lo + hi) >> 1; if (key[m] <  v0) lo = m + 1; else hi = m; }
    int k0 = lo;
    lo = 0; hi = N_;
    while (lo < hi) { int m = (lo + hi) >> 1; if (key[m] <= v1) lo = m + 1; else hi = m; }
    g_k0[b * N_ + t] = k0;
    g_k1[b * N_ + t] = lo;
}

// prefix sums of S0 rows in sorted order (per batch, per channel)
__global__ void k_prefix() {
    int b = blockIdx.x, t = threadIdx.x;   // 256 threads
    float run = 0.f;
    g_P[(b * (N_ + 1)) * D_ + t] = 0.f;
    const int* si = &g_sidx[b * N_];
    for (int m = 0; m < N_; m++) {
        run += g_S0[(b * N_ + si[m]) * D_ + t];
        g_P[(b * (N_ + 1) + m + 1) * D_ + t] = run;
    }
}

// build stacked weight matrix: rows [0,1536)=rel_W, [1536,1542)=rel_b, rest 0
__global__ void k_wfull(const float* __restrict__ relW, const float* __restrict__ relb) {
    int idx = blockIdx.x * 256 + threadIdx.x;
    if (idx >= KA_ * D_) return;
    int row = idx / D_, e = idx % D_;
    float v;
    if (row < R_ * D_)            v = relW[idx];
    else if (row < R_ * D_ + R_)  v = relb[(row - R_ * D_) * D_ + e];
    else                          v = 0.f;
    g_Wfull[idx] = v;
}

// per-(batch, 8 sorted targets) band accumulation -> A rows (incl counts)
__global__ void k_band(const float* __restrict__ pos) {
    __shared__ int   sidx_s[N_];
    __shared__ float xs[N_], ys[N_];
    __shared__ unsigned char codes[N_ * 8];
    __shared__ int cnt[8][4];
    __shared__ float sS[16][D_];
    __shared__ int kk0[8], kk1[8], oj[8];
    __shared__ float xj[8], yj[8];

    int b    = blockIdx.x >> 6;    // /64
    int tile = blockIdx.x & 63;
    int t0   = tile * 8;
    int t    = threadIdx.x;        // 256

    for (int m = t; m < N_; m += 256) {
        int i = g_sidx[b * N_ + m];
        sidx_s[m] = i;
        xs[m] = pos[(b * N_ + i) * 2 + 0];
        ys[m] = pos[(b * N_ + i) * 2 + 1];
    }
    if (t < 8) { kk0[t] = g_k0[b * N_ + t0 + t]; kk1[t] = g_k1[b * N_ + t0 + t]; }
    if (t < 32) cnt[t >> 2][t & 3] = 0;
    __syncthreads();
    if (t < 8) { xj[t] = xs[t0 + t]; yj[t] = ys[t0 + t]; oj[t] = sidx_s[t0 + t]; }
    __syncthreads();

    int mlo = kk0[0], mhi = kk1[0];
#pragma unroll
    for (int jt = 1; jt < 8; jt++) { mlo = min(mlo, kk0[jt]); mhi = max(mhi, kk1[jt]); }

    // classify union band: codes 2..5 (in-band non-self), 255 otherwise
    for (int idx = t; idx < (mhi - mlo) * 8; idx += 256) {
        int m  = mlo + (idx >> 3);
        int jt = idx & 7;
        unsigned char c = 255;
        if (m >= kk0[jt] && m < kk1[jt] && m != t0 + jt) {
            float dx = xj[jt] - xs[m];
            float dy = yj[jt] - ys[m];
            if (dx < -0.5f)                               c = 2;
            else if (dx > 0.5f)                           c = 3;
            else if (fabsf(dx) < 0.3f && fabsf(dy) < 0.3f) c = 4;
            else                                          c = 5;
            if (c < 5) atomicAdd(&cnt[jt][c - 2], 1);
        }
        codes[m * 8 + jt] = c;
    }
    __syncthreads();

    float a2[8], a3[8], a4[8];
#pragma unroll
    for (int jt = 0; jt < 8; jt++) { a2[jt] = 0.f; a3[jt] = 0.f; a4[jt] = 0.f; }

    for (int mb = mlo; mb < mhi; mb += 16) {
        int nrows = min(16, mhi - mb);
        for (int ii = 0; ii < nrows; ii++)
            sS[ii][t] = g_S0[(b * N_ + sidx_s[mb + ii]) * D_ + t];
        __syncthreads();
        for (int ii = 0; ii < nrows; ii++) {
            float s = sS[ii][t];
            uint2 cw = *(const uint2*)&codes[(mb + ii) * 8];
#pragma unroll
            for (int jt = 0; jt < 8; jt++) {
                unsigned int word = (jt < 4) ? cw.x : cw.y;
                unsigned int c = (word >> ((jt & 3) * 8)) & 255u;
                if (c == 2)      a2[jt] += s;
                else if (c == 3) a3[jt] += s;
                else if (c == 4) a4[jt] += s;
            }
        }
        __syncthreads();
    }

    // write A rows: r0/r1 from prefix table, r2..4 accumulated, r5 derived, counts appended
    const float* Pb = &g_P[b * (N_ + 1) * D_];
    float tot = Pb[N_ * D_ + t];
#pragma unroll
    for (int jt = 0; jt < 8; jt++) {
        int j = oj[jt];
        float p0 = Pb[kk0[jt] * D_ + t];
        float p1 = Pb[kk1[jt] * D_ + t];
        float sj = g_S0[(b * N_ + j) * D_ + t];
        float bandtot = p1 - p0 - sj;
        float* Ar = &g_A[(size_t)(b * N_ + j) * KA_];
        Ar[0 * D_ + t] = p0;
        Ar[1 * D_ + t] = tot - p1;
        Ar[2 * D_ + t] = a2[jt];
        Ar[3 * D_ + t] = a3[jt];
        Ar[4 * D_ + t] = a4[jt];
        Ar[5 * D_ + t] = bandtot - a2[jt] - a3[jt] - a4[jt];
        if (t < 16) {
            float cv = 0.f;
            if (t == 0)      cv = (float)kk0[jt];
            else if (t == 1) cv = (float)(N_ - kk1[jt]);
            else if (t == 2) cv = (float)cnt[jt][0];
            else if (t == 3) cv = (float)cnt[jt][1];
            else if (t == 4) cv = (float)cnt[jt][2];
            else if (t == 5) cv = (float)((kk1[jt] - kk0[jt] - 1) - cnt[jt][0] - cnt[jt][1] - cnt[jt][2]);
            Ar[R_ * D_ + t] = cv;   // cols 1536..1551 (pads zeroed)
        }
    }
}

// tiled fp32 GEMM: C[row, coff+col] = epilogue(A[M,K] @ B[K,N])
// BM=128, BN=64, BK=16, 256 threads, 8x4 per-thread tile. K % 16 == 0, M % 128 == 0, N % 64 == 0.
template<bool ADD, bool BIAS, bool GELU_>
__global__ void sgemm(const float* __restrict__ A, int lda,
                      const float* __restrict__ Bm, int ldb,
                      float* __restrict__ C, int ldc, int coff,
                      int K,
                      const float* __restrict__ addp,
                      const float* __restrict__ biasp) {
    const int BK = 16;
    __shared__ float As[BK][128];
    __shared__ float Bs[BK][64];
    int t   = threadIdx.x;
    int bm0 = blockIdx.y * 128;
    int bn0 = blockIdx.x * 64;
    int tx  = t & 15, ty = t >> 4;

    float acc[8][4];
#pragma unroll
    for (int i = 0; i < 8; i++)
#pragma unroll
        for (int j = 0; j < 4; j++) acc[i][j] = 0.f;

    int ar  = t >> 2;            // 0..63 (plus +64 for second load)
    int ac4 = (t & 3) * 4;       // k offset 0,4,8,12
    int br  = t >> 4;            // 0..15 (k row)
    int bc  = (t & 15) * 4;      // col offset

    for (int kt = 0; kt < K; kt += BK) {
#pragma unroll
        for (int l = 0; l < 2; l++) {
            int r = ar + l * 64;
            float4 v = *(const float4*)&A[(size_t)(bm0 + r) * lda + kt + ac4];
            As[ac4 + 0][r] = v.x; As[ac4 + 1][r] = v.y;
            As[ac4 + 2][r] = v.z; As[ac4 + 3][r] = v.w;
        }
        float4 bv = *(const float4*)&Bm[(size_t)(kt + br) * ldb + bn0 + bc];
        *(float4*)&Bs[br][bc] = bv;
        __syncthreads();
#pragma unroll
        for (int kk = 0; kk < BK; kk++) {
            float4 a0 = *(const float4*)&As[kk][ty * 8];
            float4 a1 = *(const float4*)&As[kk][ty * 8 + 4];
            float4 bb = *(const float4*)&Bs[kk][tx * 4];
            float av[8] = {a0.x, a0.y, a0.z, a0.w, a1.x, a1.y, a1.z, a1.w};
            float bw[4] = {bb.x, bb.y, bb.z, bb.w};
#pragma unroll
            for (int im = 0; im < 8; im++)
#pragma unroll
                for (int in = 0; in < 4; in++)
                    acc[im][in] += av[im] * bw[in];
        }
        __syncthreads();
    }

#pragma unroll
    for (int im = 0; im < 8; im++) {
        int row = bm0 + ty * 8 + im;
#pragma unroll
        for (int in = 0; in < 4; in++) {
            int col = bn0 + tx * 4 + in;
            float v = acc[im][in];
            if (BIAS) v += biasp[col];
            if (ADD)  v += addp[(size_t)row * D_ + col];
            if (GELU_) v = 0.5f * v * (1.f + erff(v * 0.70710678118654752440f));
            C[(size_t)row * ldc + coff + col] = v;
        }
    }
}

// interp[b,n,r] = H[row, r*256:..] . h2_W[r] + h2_b[r]
__global__ void k_interp(const float* __restrict__ h2W, const float* __restrict__ h2b,
                         float* __restrict__ out) {
    int row  = blockIdx.x;
    int wid  = threadIdx.x >> 5;   // head (3 warps)
    int lane = threadIdx.x & 31;
    const float* hrow = &g_H[(size_t)row * (3 * D_) + wid * D_];
    const float* w    = &h2W[wid * D_];
    float s = 0.f;
    for (int e = lane; e < D_; e += 32) s += hrow[e] * w[e];
#pragma unroll
    for (int o = 16; o; o >>= 1) s += __shfl_xor_sync(0xffffffffu, s, o);
    if (lane == 0) out[OFF_INTERP + wid * BN_ + row] = s + h2b[wid];
}

// ---------------- launch ----------------
extern "C" void kernel_launch(void* const* d_in, const int* in_sizes, int n_in,
                              void* d_out, int out_size) {
    const int*   ids  = (const int*)  d_in[0];
    const float* pos  = (const float*)d_in[1];
    const float* symt = (const float*)d_in[2];
    const float* layt = (const float*)d_in[3];
    const float* relW = (const float*)d_in[4];
    const float* relb = (const float*)d_in[5];
    const float* h1W  = (const float*)d_in[6];
    const float* h1b  = (const float*)d_in[7];
    const float* h2W  = (const float*)d_in[8];
    const float* h2b  = (const float*)d_in[9];
    const float* outW = (const float*)d_in[10];
    const float* outb = (const float*)d_in[11];
    float* out = (float*)d_out;

    float *pA, *pW, *pH, *pS0;
    cudaGetSymbolAddress((void**)&pA,  g_A);
    cudaGetSymbolAddress((void**)&pW,  g_Wfull);
    cudaGetSymbolAddress((void**)&pH,  g_H);
    cudaGetSymbolAddress((void**)&pS0, g_S0);

    k_embed <<<BN_, D_>>>(ids, symt, layt);
    k_sort  <<<B_, N_>>>(pos);
    k_prefix<<<B_, D_>>>();
    k_wfull <<<(KA_ * D_ + 255) / 256, 256>>>(relW, relb);
    k_band  <<<B_ * 64, 256>>>(pos);

    float* d_sym = out + OFF_SYM;
    // grammar: symbols = S0 + A @ Wfull (bias folded via count columns)
    sgemm<true, false, false><<<dim3(D_ / 64, BN_ / 128), 256>>>(
        pA, KA_, pW, D_, d_sym, D_, 0, KA_, pS0, nullptr);
    // interpretation heads: H = gelu(symbols @ h1_W[r] + h1_b[r])
    for (int r = 0; r < 3; r++)
        sgemm<false, true, true><<<dim3(D_ / 64, BN_ / 128), 256>>>(
            d_sym, D_, h1W + (size_t)r * D_ * D_, D_, pH, 3 * D_, r * D_, D_,
            nullptr, h1b + r * D_);
    // output projection
    sgemm<false, true, false><<<dim3(D_ / 64, BN_ / 128), 256>>>(
        d_sym, D_, outW, D_, out, D_, 0, D_, nullptr, outb);

    k_interp<<<BN_, 96>>>(h2W, h2b, out);
}

// round 7
// speedup vs baseline: 1.1065x; 1.1065x over previous
#include <cuda_runtime.h>
#include <math.h>
#include <stdint.h>

// Problem constants
#define B_   8
#define N_   512
#define D_   256
#define R_   6
#define BN_  (B_*N_)          // 4096 rows
#define KA_  1568             // 6*256 rel cols + 6 count cols + 26 zero pad (mult of 32)

// Output layout in d_out (floats)
#define OFF_INTERP 1048576
#define OFF_SYM    (1048576 + 3*4096)

// ---------------- scratch ----------------
__device__ float g_S0[BN_ * D_];
__device__ float g_A[BN_ * KA_];
__device__ float g_Wfull[KA_ * D_];
__device__ float g_H[BN_ * 3 * D_];
__device__ float g_P[B_ * (N_ + 1) * D_];
__device__ float g_ysort[B_ * N_];
__device__ int   g_sidx[B_ * N_];
__device__ int   g_k0[B_ * N_];
__device__ int   g_k1[B_ * N_];

// ---------------- small kernels ----------------
__global__ void k_embed(const int* __restrict__ ids,
                        const float* __restrict__ symt,
                        const float* __restrict__ layt) {
    int row = blockIdx.x, t = threadIdx.x;
    int id  = ids[row];
    g_S0[row * D_ + t] = symt[id * D_ + t] + layt[id * D_ + t];
}

__global__ void k_sort(const float* __restrict__ pos) {
    __shared__ float key[N_];
    __shared__ int   val[N_];
    int b = blockIdx.x, t = threadIdx.x;
    key[t] = pos[(b * N_ + t) * 2 + 1];
    val[t] = t;
    __syncthreads();
    for (int size = 2; size <= N_; size <<= 1) {
        for (int stride = size >> 1; stride > 0; stride >>= 1) {
            int j = t ^ stride;
            if (j > t) {
                bool up = ((t & size) == 0);
                float kt = key[t], kj = key[j];
                if ((kt > kj) == up) {
                    key[t] = kj; key[j] = kt;
                    int vt = val[t]; val[t] = val[j]; val[j] = vt;
                }
            }
            __syncthreads();
        }
    }
    g_ysort[b * N_ + t] = key[t];
    g_sidx[b * N_ + t]  = val[t];
    float y  = key[t];
    float v0 = y - 0.5f, v1 = y + 0.5f;
    int lo = 0, hi = N_;
    while (lo < hi) { int m = (lo + hi) >> 1; if (key[m] <  v0) lo = m + 1; else hi = m; }
    int k0 = lo;
    lo = 0; hi = N_;
    while (lo < hi) { int m = (lo + hi) >> 1; if (key[m] <= v1) lo = m + 1; else hi = m; }
    g_k0[b * N_ + t] = k0;
    g_k1[b * N_ + t] = lo;
}

__global__ void k_prefix() {
    int b = blockIdx.x, t = threadIdx.x;
    float run = 0.f;
    g_P[(b * (N_ + 1)) * D_ + t] = 0.f;
    const int* si = &g_sidx[b * N_];
    for (int m = 0; m < N_; m++) {
        run += g_S0[(b * N_ + si[m]) * D_ + t];
        g_P[(b * (N_ + 1) + m + 1) * D_ + t] = run;
    }
}

__global__ void k_wfull(const float* __restrict__ relW, const float* __restrict__ relb) {
    int idx = blockIdx.x * 256 + threadIdx.x;
    if (idx >= KA_ * D_) return;
    int row = idx / D_, e = idx % D_;
    float v;
    if (row < R_ * D_)            v = relW[idx];
    else if (row < R_ * D_ + R_)  v = relb[(row - R_ * D_) * D_ + e];
    else                          v = 0.f;
    g_Wfull[idx] = v;
}

__global__ void k_band(const float* __restrict__ pos) {
    __shared__ int   sidx_s[N_];
    __shared__ float xs[N_], ys[N_];
    __shared__ unsigned char codes[N_ * 8];
    __shared__ int cnt[8][4];
    __shared__ float sS[16][D_];
    __shared__ int kk0[8], kk1[8], oj[8];
    __shared__ float xj[8], yj[8];

    int b    = blockIdx.x >> 6;
    int tile = blockIdx.x & 63;
    int t0   = tile * 8;
    int t    = threadIdx.x;

    for (int m = t; m < N_; m += 256) {
        int i = g_sidx[b * N_ + m];
        sidx_s[m] = i;
        xs[m] = pos[(b * N_ + i) * 2 + 0];
        ys[m] = pos[(b * N_ + i) * 2 + 1];
    }
    if (t < 8) { kk0[t] = g_k0[b * N_ + t0 + t]; kk1[t] = g_k1[b * N_ + t0 + t]; }
    if (t < 32) cnt[t >> 2][t & 3] = 0;
    __syncthreads();
    if (t < 8) { xj[t] = xs[t0 + t]; yj[t] = ys[t0 + t]; oj[t] = sidx_s[t0 + t]; }
    __syncthreads();

    int mlo = kk0[0], mhi = kk1[0];
#pragma unroll
    for (int jt = 1; jt < 8; jt++) { mlo = min(mlo, kk0[jt]); mhi = max(mhi, kk1[jt]); }

    for (int idx = t; idx < (mhi - mlo) * 8; idx += 256) {
        int m  = mlo + (idx >> 3);
        int jt = idx & 7;
        unsigned char c = 255;
        if (m >= kk0[jt] && m < kk1[jt] && m != t0 + jt) {
            float dx = xj[jt] - xs[m];
            float dy = yj[jt] - ys[m];
            if (dx < -0.5f)                                c = 2;
            else if (dx > 0.5f)                            c = 3;
            else if (fabsf(dx) < 0.3f && fabsf(dy) < 0.3f) c = 4;
            else                                           c = 5;
            if (c < 5) atomicAdd(&cnt[jt][c - 2], 1);
        }
        codes[m * 8 + jt] = c;
    }
    __syncthreads();

    float a2[8], a3[8], a4[8];
#pragma unroll
    for (int jt = 0; jt < 8; jt++) { a2[jt] = 0.f; a3[jt] = 0.f; a4[jt] = 0.f; }

    for (int mb = mlo; mb < mhi; mb += 16) {
        int nrows = min(16, mhi - mb);
        for (int ii = 0; ii < nrows; ii++)
            sS[ii][t] = g_S0[(b * N_ + sidx_s[mb + ii]) * D_ + t];
        __syncthreads();
        for (int ii = 0; ii < nrows; ii++) {
            float s = sS[ii][t];
            uint2 cw = *(const uint2*)&codes[(mb + ii) * 8];
#pragma unroll
            for (int jt = 0; jt < 8; jt++) {
                unsigned int word = (jt < 4) ? cw.x : cw.y;
                unsigned int c = (word >> ((jt & 3) * 8)) & 255u;
                if (c == 2)      a2[jt] += s;
                else if (c == 3) a3[jt] += s;
                else if (c == 4) a4[jt] += s;
            }
        }
        __syncthreads();
    }

    const float* Pb = &g_P[b * (N_ + 1) * D_];
    float tot = Pb[N_ * D_ + t];
#pragma unroll
    for (int jt = 0; jt < 8; jt++) {
        int j = oj[jt];
        float p0 = Pb[kk0[jt] * D_ + t];
        float p1 = Pb[kk1[jt] * D_ + t];
        float sj = g_S0[(b * N_ + j) * D_ + t];
        float bandtot = p1 - p0 - sj;
        float* Ar = &g_A[(size_t)(b * N_ + j) * KA_];
        Ar[0 * D_ + t] = p0;
        Ar[1 * D_ + t] = tot - p1;
        Ar[2 * D_ + t] = a2[jt];
        Ar[3 * D_ + t] = a3[jt];
        Ar[4 * D_ + t] = a4[jt];
        Ar[5 * D_ + t] = bandtot - a2[jt] - a3[jt] - a4[jt];
        if (t < 32) {   // cols 1536..1567: 6 counts then zero pad
            float cv = 0.f;
            if (t == 0)      cv = (float)kk0[jt];
            else if (t == 1) cv = (float)(N_ - kk1[jt]);
            else if (t == 2) cv = (float)cnt[jt][0];
            else if (t == 3) cv = (float)cnt[jt][1];
            else if (t == 4) cv = (float)cnt[jt][2];
            else if (t == 5) cv = (float)((kk1[jt] - kk0[jt] - 1) - cnt[jt][0] - cnt[jt][1] - cnt[jt][2]);
            Ar[R_ * D_ + t] = cv;
        }
    }
}

// ---------------- tf32 tensor-core GEMM (3xTF32 compensation) ----------------
__device__ __forceinline__ uint32_t f2tf32(float x) {
    uint32_t r;
    asm("cvt.rna.tf32.f32 %0, %1;" : "=r"(r) : "f"(x));
    return r;
}

__device__ __forceinline__ void mma_tf32(float* c, uint32_t a0, uint32_t a1,
                                         uint32_t a2, uint32_t a3,
                                         uint32_t b0, uint32_t b1) {
    asm volatile(
        "mma.sync.aligned.m16n8k8.row.col.f32.tf32.tf32.f32 "
        "{%0,%1,%2,%3}, {%4,%5,%6,%7}, {%8,%9}, {%0,%1,%2,%3};"
        : "+f"(c[0]), "+f"(c[1]), "+f"(c[2]), "+f"(c[3])
        : "r"(a0), "r"(a1), "r"(a2), "r"(a3), "r"(b0), "r"(b1));
}

// BM=128, BN=64, BK=32, 256 threads (8 warps, 4x2 layout).
// C[row, coff+col] = epi(A[M,K] @ Bm[K,N]); K%32==0.
template<bool ADD, bool BIAS, bool GELU_>
__global__ void __launch_bounds__(256, 2) mgemm(
        const float* __restrict__ A, int lda,
        const float* __restrict__ Bm, int ldb,
        float* __restrict__ C, int ldc, int coff,
        int K,
        const float* __restrict__ addp,
        const float* __restrict__ biasp) {
    __shared__ float As[128 * 36];   // [row][k], stride 36
    __shared__ float Bs[64 * 36];    // [n][k],   stride 36 (transposed)

    int t    = threadIdx.x;
    int warp = t >> 5, lane = t & 31;
    int wm   = warp >> 1;            // 0..3 -> 32-row slab
    int wn   = warp & 1;             // 0..1 -> 32-col slab
    int bm0  = blockIdx.y * 128;
    int bn0  = blockIdx.x * 64;

    int qr = lane >> 2;              // 0..7
    int qc = lane & 3;               // 0..3

    float acc[2][4][4];
#pragma unroll
    for (int mt = 0; mt < 2; mt++)
#pragma unroll
        for (int nt = 0; nt < 4; nt++)
#pragma unroll
            for (int f = 0; f < 4; f++) acc[mt][nt][f] = 0.f;

    // A tile load mapping: 1024 float4 / 256 thr = 4 each
    int a_row = t >> 1;              // rows t/2 and +... handled in loop
    // B tile load mapping: 2048 floats / 256 = 8 each

    for (int kt = 0; kt < K; kt += 32) {
        // load A [128 x 32]
#pragma unroll
        for (int l = 0; l < 4; l++) {
            int id  = t + l * 256;           // 0..1023
            int row = id >> 3;
            int kq  = (id & 7) * 4;
            float4 v = *(const float4*)&A[(size_t)(bm0 + row) * lda + kt + kq];
            *(float4*)&As[row * 36 + kq] = v;
        }
        // load B [32 x 64] transposed -> Bs[n][k]
#pragma unroll
        for (int l = 0; l < 8; l++) {
            int id = t + l * 256;            // 0..2047
            int k  = id >> 6;
            int n  = id & 63;
            Bs[n * 36 + k] = Bm[(size_t)(kt + k) * ldb + bn0 + n];
        }
        __syncthreads();

#pragma unroll
        for (int ks = 0; ks < 32; ks += 8) {
            int k0 = ks + qc;
            // A fragments (2 m-tiles x 4 elems)
            uint32_t ahi[8], alo[8];
#pragma unroll
            for (int mt = 0; mt < 2; mt++) {
                int rb = wm * 32 + mt * 16 + qr;
                float e0 = As[rb * 36 + k0];
                float e1 = As[(rb + 8) * 36 + k0];
                float e2 = As[rb * 36 + k0 + 4];
                float e3 = As[(rb + 8) * 36 + k0 + 4];
                float fe[4] = {e0, e1, e2, e3};
#pragma unroll
                for (int f = 0; f < 4; f++) {
                    uint32_t h = f2tf32(fe[f]);
                    ahi[mt * 4 + f] = h;
                    alo[mt * 4 + f] = f2tf32(fe[f] - __uint_as_float(h));
                }
            }
            // B fragments (4 n-tiles x 2 elems)
            uint32_t bhi[8], blo[8];
#pragma unroll
            for (int nt = 0; nt < 4; nt++) {
                int nb = wn * 32 + nt * 8 + qr;
                float e0 = Bs[nb * 36 + k0];
                float e1 = Bs[nb * 36 + k0 + 4];
                uint32_t h0 = f2tf32(e0), h1 = f2tf32(e1);
                bhi[nt * 2 + 0] = h0;
                bhi[nt * 2 + 1] = h1;
                blo[nt * 2 + 0] = f2tf32(e0 - __uint_as_float(h0));
                blo[nt * 2 + 1] = f2tf32(e1 - __uint_as_float(h1));
            }
#pragma unroll
            for (int mt = 0; mt < 2; mt++)
#pragma unroll
                for (int nt = 0; nt < 4; nt++) {
                    float* c = acc[mt][nt];
                    mma_tf32(c, ahi[mt*4], ahi[mt*4+1], ahi[mt*4+2], ahi[mt*4+3],
                             bhi[nt*2], bhi[nt*2+1]);
                    mma_tf32(c, alo[mt*4], alo[mt*4+1], alo[mt*4+2], alo[mt*4+3],
                             bhi[nt*2], bhi[nt*2+1]);
                    mma_tf32(c, ahi[mt*4], ahi[mt*4+1], ahi[mt*4+2], ahi[mt*4+3],
                             blo[nt*2], blo[nt*2+1]);
                }
        }
        __syncthreads();
    }

    // epilogue
#pragma unroll
    for (int mt = 0; mt < 2; mt++) {
#pragma unroll
        for (int f = 0; f < 4; f++) {
            int row = bm0 + wm * 32 + mt * 16 + qr + ((f >= 2) ? 8 : 0);
#pragma unroll
            for (int nt = 0; nt < 4; nt++) {
                int col = bn0 + wn * 32 + nt * 8 + qc * 2 + (f & 1);
                float v = acc[mt][nt][f];
                if (BIAS) v += biasp[col];
                if (ADD)  v += addp[(size_t)row * D_ + col];
                if (GELU_) v = 0.5f * v * (1.f + erff(v * 0.70710678118654752440f));
                C[(size_t)row * ldc + coff + col] = v;
            }
        }
    }
}

__global__ void k_interp(const float* __restrict__ h2W, const float* __restrict__ h2b,
                         float* __restrict__ out) {
    int row  = blockIdx.x;
    int wid  = threadIdx.x >> 5;
    int lane = threadIdx.x & 31;
    const float* hrow = &g_H[(size_t)row * (3 * D_) + wid * D_];
    const float* w    = &h2W[wid * D_];
    float s = 0.f;
    for (int e = lane; e < D_; e += 32) s += hrow[e] * w[e];
#pragma unroll
    for (int o = 16; o; o >>= 1) s += __shfl_xor_sync(0xffffffffu, s, o);
    if (lane == 0) out[OFF_INTERP + wid * BN_ + row] = s + h2b[wid];
}

// ---------------- launch ----------------
extern "C" void kernel_launch(void* const* d_in, const int* in_sizes, int n_in,
                              void* d_out, int out_size) {
    const int*   ids  = (const int*)  d_in[0];
    const float* pos  = (const float*)d_in[1];
    const float* symt = (const float*)d_in[2];
    const float* layt = (const float*)d_in[3];
    const float* relW = (const float*)d_in[4];
    const float* relb = (const float*)d_in[5];
    const float* h1W  = (const float*)d_in[6];
    const float* h1b  = (const float*)d_in[7];
    const float* h2W  = (const float*)d_in[8];
    const float* h2b  = (const float*)d_in[9];
    const float* outW = (const float*)d_in[10];
    const float* outb = (const float*)d_in[11];
    float* out = (float*)d_out;

    float *pA, *pW, *pH, *pS0;
    cudaGetSymbolAddress((void**)&pA,  g_A);
    cudaGetSymbolAddress((void**)&pW,  g_Wfull);
    cudaGetSymbolAddress((void**)&pH,  g_H);
    cudaGetSymbolAddress((void**)&pS0, g_S0);

    k_embed <<<BN_, D_>>>(ids, symt, layt);
    k_sort  <<<B_, N_>>>(pos);
    k_prefix<<<B_, D_>>>();
    k_wfull <<<(KA_ * D_ + 255) / 256, 256>>>(relW, relb);
    k_band  <<<B_ * 64, 256>>>(pos);

    float* d_sym = out + OFF_SYM;
    // grammar: symbols = S0 + A @ Wfull
    mgemm<true, false, false><<<dim3(D_ / 64, BN_ / 128), 256>>>(
        pA, KA_, pW, D_, d_sym, D_, 0, KA_, pS0, nullptr);
    // heads: H = gelu(symbols @ h1_W[r] + h1_b[r])
    for (int r = 0; r < 3; r++)
        mgemm<false, true, true><<<dim3(D_ / 64, BN_ / 128), 256>>>(
            d_sym, D_, h1W + (size_t)r * D_ * D_, D_, pH, 3 * D_, r * D_, D_,
            nullptr, h1b + r * D_);
    // output projection
    mgemm<false, true, false><<<dim3(D_ / 64, BN_ / 128), 256>>>(
        d_sym, D_, outW, D_, out, D_, 0, D_, nullptr, outb);

    k_interp<<<BN_, 96>>>(h2W, h2b, out);
}

// round 9
// speedup vs baseline: 1.5606x; 1.4104x over previous
#include <cuda_runtime.h>
#include <math.h>
#include <stdint.h>

// Problem constants
#define B_   8
#define N_   512
#define D_   256
#define R_   6
#define BN_  (B_*N_)          // 4096 rows
#define KA_  1568             // 6*256 rel cols + 6 count cols + 26 zero pad (mult of 32)

// Output layout in d_out (floats)
#define OFF_INTERP 1048576
#define OFF_SYM    (1048576 + 3*4096)

// ---------------- scratch ----------------
__device__ float g_S0[BN_ * D_];
__device__ float g_A[BN_ * KA_];
__device__ float g_Wfull[KA_ * D_];
__device__ float g_Wcat[D_ * 4 * D_];       // [k][1024]: 3 head W's + outW
__device__ float g_bcat[4 * D_];
__device__ float g_H[BN_ * 3 * D_];
__device__ float g_P[B_ * (N_ + 1) * D_];
__device__ float g_ysort[B_ * N_];
__device__ int   g_sidx[B_ * N_];
__device__ int   g_k0[B_ * N_];
__device__ int   g_k1[B_ * N_];

// ---------------- small kernels ----------------
__global__ void k_embed(const int* __restrict__ ids,
                        const float* __restrict__ symt,
                        const float* __restrict__ layt) {
    int row = blockIdx.x, t = threadIdx.x;
    int id  = ids[row];
    g_S0[row * D_ + t] = symt[id * D_ + t] + layt[id * D_ + t];
}

__global__ void k_sort(const float* __restrict__ pos) {
    __shared__ float key[N_];
    __shared__ int   val[N_];
    int b = blockIdx.x, t = threadIdx.x;
    key[t] = pos[(b * N_ + t) * 2 + 1];
    val[t] = t;
    __syncthreads();
    for (int size = 2; size <= N_; size <<= 1) {
        for (int stride = size >> 1; stride > 0; stride >>= 1) {
            int j = t ^ stride;
            if (j > t) {
                bool up = ((t & size) == 0);
                float kt = key[t], kj = key[j];
                if ((kt > kj) == up) {
                    key[t] = kj; key[j] = kt;
                    int vt = val[t]; val[t] = val[j]; val[j] = vt;
                }
            }
            __syncthreads();
        }
    }
    g_ysort[b * N_ + t] = key[t];
    g_sidx[b * N_ + t]  = val[t];
    float y  = key[t];
    float v0 = y - 0.5f, v1 = y + 0.5f;
    int lo = 0, hi = N_;
    while (lo < hi) { int m = (lo + hi) >> 1; if (key[m] <  v0) lo = m + 1; else hi = m; }
    int k0 = lo;
    lo = 0; hi = N_;
    while (lo < hi) { int m = (lo + hi) >> 1; if (key[m] <= v1) lo = m + 1; else hi = m; }
    g_k0[b * N_ + t] = k0;
    g_k1[b * N_ + t] = lo;
}

// segmented parallel prefix: grid = B*8 (8 channel groups of 32), block = 256
// (8 row-segments of 64 x 32 channels, one warp per segment)
__global__ void k_prefix() {
    __shared__ float ssum[8][32];
    int b   = blockIdx.x >> 3;
    int g   = blockIdx.x & 7;
    int ch  = (threadIdx.x & 31) + g * 32;
    int seg = threadIdx.x >> 5;
    const int* si = &g_sidx[b * N_];
    int m0 = seg * 64;
    float s = 0.f;
#pragma unroll 4
    for (int m = 0; m < 64; m++)
        s += g_S0[(b * N_ + si[m0 + m]) * D_ + ch];
    ssum[seg][threadIdx.x & 31] = s;
    __syncthreads();
    float run = 0.f;
    for (int q = 0; q < seg; q++) run += ssum[q][threadIdx.x & 31];
    float* Pb = &g_P[(size_t)(b * (N_ + 1)) * D_ + ch];
#pragma unroll 4
    for (int m = 0; m < 64; m++) {
        Pb[(size_t)(m0 + m) * D_] = run;
        run += g_S0[(b * N_ + si[m0 + m]) * D_ + ch];
    }
    if (seg == 7) Pb[(size_t)N_ * D_] = run;
}

__global__ void k_wfull(const float* __restrict__ relW, const float* __restrict__ relb) {
    int idx = blockIdx.x * 256 + threadIdx.x;
    if (idx >= KA_ * D_) return;
    int row = idx / D_, e = idx % D_;
    float v;
    if (row < R_ * D_)            v = relW[idx];
    else if (row < R_ * D_ + R_)  v = relb[(row - R_ * D_) * D_ + e];
    else                          v = 0.f;
    g_Wfull[idx] = v;
}

// concat 3 head weights + output weight into [256 x 1024], plus bias vector
__global__ void k_wcat(const float* __restrict__ h1W, const float* __restrict__ h1b,
                       const float* __restrict__ outW, const float* __restrict__ outb) {
    int idx = blockIdx.x * 256 + threadIdx.x;   // 0 .. 256*1024-1
    int k = idx >> 10, n = idx & 1023;
    float v = (n < 768) ? h1W[((n >> 8) * D_ + k) * D_ + (n & 255)]
                        : outW[k * D_ + (n - 768)];
    g_Wcat[idx] = v;
    if (idx < 1024)
        g_bcat[idx] = (idx < 768) ? h1b[(idx >> 8) * D_ + (idx & 255)] : outb[idx - 768];
}

__global__ void k_band(const float* __restrict__ pos) {
    __shared__ int   sidx_s[N_];
    __shared__ float xs[N_], ys[N_];
    __shared__ unsigned char codes[N_ * 8];
    __shared__ int cnt[8][4];
    __shared__ float sS[16][D_];
    __shared__ int kk0[8], kk1[8], oj[8];
    __shared__ float xj[8], yj[8];

    int b    = blockIdx.x >> 6;
    int tile = blockIdx.x & 63;
    int t0   = tile * 8;
    int t    = threadIdx.x;

    for (int m = t; m < N_; m += 256) {
        int i = g_sidx[b * N_ + m];
        sidx_s[m] = i;
        xs[m] = pos[(b * N_ + i) * 2 + 0];
        ys[m] = pos[(b * N_ + i) * 2 + 1];
    }
    if (t < 8) { kk0[t] = g_k0[b * N_ + t0 + t]; kk1[t] = g_k1[b * N_ + t0 + t]; }
    if (t < 32) cnt[t >> 2][t & 3] = 0;
    __syncthreads();
    if (t < 8) { xj[t] = xs[t0 + t]; yj[t] = ys[t0 + t]; oj[t] = sidx_s[t0 + t]; }
    __syncthreads();

    int mlo = kk0[0], mhi = kk1[0];
#pragma unroll
    for (int jt = 1; jt < 8; jt++) { mlo = min(mlo, kk0[jt]); mhi = max(mhi, kk1[jt]); }

    for (int idx = t; idx < (mhi - mlo) * 8; idx += 256) {
        int m  = mlo + (idx >> 3);
        int jt = idx & 7;
        unsigned char c = 255;
        if (m >= kk0[jt] && m < kk1[jt] && m != t0 + jt) {
            float dx = xj[jt] - xs[m];
            float dy = yj[jt] - ys[m];
            if (dx < -0.5f)                                c = 2;
            else if (dx > 0.5f)                            c = 3;
            else if (fabsf(dx) < 0.3f && fabsf(dy) < 0.3f) c = 4;
            else                                           c = 5;
            if (c < 5) atomicAdd(&cnt[jt][c - 2], 1);
        }
        codes[m * 8 + jt] = c;
    }
    __syncthreads();

    float a2[8], a3[8], a4[8];
#pragma unroll
    for (int jt = 0; jt < 8; jt++) { a2[jt] = 0.f; a3[jt] = 0.f; a4[jt] = 0.f; }

    for (int mb = mlo; mb < mhi; mb += 16) {
        int nrows = min(16, mhi - mb);
        for (int ii = 0; ii < nrows; ii++)
            sS[ii][t] = g_S0[(b * N_ + sidx_s[mb + ii]) * D_ + t];
        __syncthreads();
        for (int ii = 0; ii < nrows; ii++) {
            float s = sS[ii][t];
            uint2 cw = *(const uint2*)&codes[(mb + ii) * 8];
#pragma unroll
            for (int jt = 0; jt < 8; jt++) {
                unsigned int word = (jt < 4) ? cw.x : cw.y;
                unsigned int c = (word >> ((jt & 3) * 8)) & 255u;
                if (c == 2)      a2[jt] += s;
                else if (c == 3) a3[jt] += s;
                else if (c == 4) a4[jt] += s;
            }
        }
        __syncthreads();
    }

    const float* Pb = &g_P[b * (N_ + 1) * D_];
    float tot = Pb[N_ * D_ + t];
#pragma unroll
    for (int jt = 0; jt < 8; jt++) {
        int j = oj[jt];
        float p0 = Pb[kk0[jt] * D_ + t];
        float p1 = Pb[kk1[jt] * D_ + t];
        float sj = g_S0[(b * N_ + j) * D_ + t];
        float bandtot = p1 - p0 - sj;
        float* Ar = &g_A[(size_t)(b * N_ + j) * KA_];
        Ar[0 * D_ + t] = p0;
        Ar[1 * D_ + t] = tot - p1;
        Ar[2 * D_ + t] = a2[jt];
        Ar[3 * D_ + t] = a3[jt];
        Ar[4 * D_ + t] = a4[jt];
        Ar[5 * D_ + t] = bandtot - a2[jt] - a3[jt] - a4[jt];
        if (t < 32) {
            float cv = 0.f;
            if (t == 0)      cv = (float)kk0[jt];
            else if (t == 1) cv = (float)(N_ - kk1[jt]);
            else if (t == 2) cv = (float)cnt[jt][0];
            else if (t == 3) cv = (float)cnt[jt][1];
            else if (t == 4) cv = (float)cnt[jt][2];
            else if (t == 5) cv = (float)((kk1[jt] - kk0[jt] - 1) - cnt[jt][0] - cnt[jt][1] - cnt[jt][2]);
            Ar[R_ * D_ + t] = cv;
        }
    }
}

// ---------------- tf32 tensor-core GEMM (3xTF32, hi/lo pre-split in smem) ----------------
__device__ __forceinline__ uint32_t f2tf32(float x) {
    uint32_t r;
    asm("cvt.rna.tf32.f32 %0, %1;" : "=r"(r) : "f"(x));
    return r;
}

__device__ __forceinline__ void mma_tf32(float* c, uint32_t a0, uint32_t a1,
                                         uint32_t a2, uint32_t a3,
                                         uint32_t b0, uint32_t b1) {
    asm volatile(
        "mma.sync.aligned.m16n8k8.row.col.f32.tf32.tf32.f32 "
        "{%0,%1,%2,%3}, {%4,%5,%6,%7}, {%8,%9}, {%0,%1,%2,%3};"
        : "+f"(c[0]), "+f"(c[1]), "+f"(c[2]), "+f"(c[3])
        : "r"(a0), "r"(a1), "r"(a2), "r"(a3), "r"(b0), "r"(b1));
}

// dynamic smem layout (uint32 words)
#define SM_AH 0
#define SM_AL (128*36)
#define SM_BH (2*128*36)
#define SM_BL (2*128*36 + 64*36)
#define SMEM_WORDS (2*128*36 + 2*64*36)
#define SMEM_BYTES (SMEM_WORDS * 4)

// MODE 0: C = A@Bm + addp  (grammar; N=256)
// MODE 1: fused heads+out  (N=1024; cols<768: gelu -> C(g_H,ld 768); else -> C2(out,ld 256))
template<int MODE>
__global__ void __launch_bounds__(256) mgemm2(
        const float* __restrict__ A, int lda,
        const float* __restrict__ Bm, int ldb, int K,
        const float* __restrict__ addp,
        float* __restrict__ C, float* __restrict__ C2) {
    extern __shared__ uint32_t sm[];
    uint32_t* AsH = sm + SM_AH;
    uint32_t* AsL = sm + SM_AL;
    uint32_t* BsH = sm + SM_BH;
    uint32_t* BsL = sm + SM_BL;

    int t    = threadIdx.x;
    int warp = t >> 5, lane = t & 31;
    int wm   = warp >> 1;            // 0..3 -> 32-row slab
    int wn   = warp & 1;             // 0..1 -> 32-col slab
    int bm0  = blockIdx.y * 128;
    int bn0  = blockIdx.x * 64;
    int qr   = lane >> 2;            // 0..7
    int qc   = lane & 3;             // 0..3

    float acc[2][4][4];
#pragma unroll
    for (int mt = 0; mt < 2; mt++)
#pragma unroll
        for (int nt = 0; nt < 4; nt++)
#pragma unroll
            for (int f = 0; f < 4; f++) acc[mt][nt][f] = 0.f;

    for (int kt = 0; kt < K; kt += 32) {
        // load+split A [128 x 32]
#pragma unroll
        for (int l = 0; l < 4; l++) {
            int id  = t + l * 256;
            int row = id >> 3;
            int kq  = (id & 7) * 4;
            float4 v = *(const float4*)&A[(size_t)(bm0 + row) * lda + kt + kq];
            float fe[4] = {v.x, v.y, v.z, v.w};
#pragma unroll
            for (int jj = 0; jj < 4; jj++) {
                uint32_t h = f2tf32(fe[jj]);
                AsH[row * 36 + kq + jj] = h;
                AsL[row * 36 + kq + jj] = f2tf32(fe[jj] - __uint_as_float(h));
            }
        }
        // load+split B [32 x 64] -> [n][k]
#pragma unroll
        for (int l = 0; l < 8; l++) {
            int id = t + l * 256;
            int k  = id >> 6;
            int n  = id & 63;
            float v = Bm[(size_t)(kt + k) * ldb + bn0 + n];
            uint32_t h = f2tf32(v);
            BsH[n * 36 + k] = h;
            BsL[n * 36 + k] = f2tf32(v - __uint_as_float(h));
        }
        __syncthreads();

#pragma unroll
        for (int ks = 0; ks < 32; ks += 8) {
            int k0 = ks + qc;
            uint32_t ahi[8], alo[8];
#pragma unroll
            for (int mt = 0; mt < 2; mt++) {
                int rb = wm * 32 + mt * 16 + qr;
                ahi[mt*4+0] = AsH[rb * 36 + k0];
                ahi[mt*4+1] = AsH[(rb + 8) * 36 + k0];
                ahi[mt*4+2] = AsH[rb * 36 + k0 + 4];
                ahi[mt*4+3] = AsH[(rb + 8) * 36 + k0 + 4];
                alo[mt*4+0] = AsL[rb * 36 + k0];
                alo[mt*4+1] = AsL[(rb + 8) * 36 + k0];
                alo[mt*4+2] = AsL[rb * 36 + k0 + 4];
                alo[mt*4+3] = AsL[(rb + 8) * 36 + k0 + 4];
            }
            uint32_t bhi[8], blo[8];
#pragma unroll
            for (int nt = 0; nt < 4; nt++) {
                int nb = wn * 32 + nt * 8 + qr;
                bhi[nt*2+0] = BsH[nb * 36 + k0];
                bhi[nt*2+1] = BsH[nb * 36 + k0 + 4];
                blo[nt*2+0] = BsL[nb * 36 + k0];
                blo[nt*2+1] = BsL[nb * 36 + k0 + 4];
            }
#pragma unroll
            for (int mt = 0; mt < 2; mt++)
#pragma unroll
                for (int nt = 0; nt < 4; nt++) {
                    float* c = acc[mt][nt];
                    mma_tf32(c, ahi[mt*4], ahi[mt*4+1], ahi[mt*4+2], ahi[mt*4+3],
                             bhi[nt*2], bhi[nt*2+1]);
                    mma_tf32(c, alo[mt*4], alo[mt*4+1], alo[mt*4+2], alo[mt*4+3],
                             bhi[nt*2], bhi[nt*2+1]);
                    mma_tf32(c, ahi[mt*4], ahi[mt*4+1], ahi[mt*4+2], ahi[mt*4+3],
                             blo[nt*2], blo[nt*2+1]);
                }
        }
        __syncthreads();
    }

    // epilogue
#pragma unroll
    for (int mt = 0; mt < 2; mt++) {
#pragma unroll
        for (int f = 0; f < 4; f++) {
            int row = bm0 + wm * 32 + mt * 16 + qr + ((f >= 2) ? 8 : 0);
#pragma unroll
            for (int nt = 0; nt < 4; nt++) {
                int col = bn0 + wn * 32 + nt * 8 + qc * 2 + (f & 1);
                float v = acc[mt][nt][f];
                if (MODE == 0) {
                    v += addp[(size_t)row * D_ + col];
                    C[(size_t)row * D_ + col] = v;
                } else {
                    v += g_bcat[col];
                    if (bn0 < 768) {
                        v = 0.5f * v * (1.f + erff(v * 0.70710678118654752440f));
                        C[(size_t)row * 768 + col] = v;
                    } else {
                        C2[(size_t)row * D_ + (col - 768)] = v;
                    }
                }
            }
        }
    }
}

__global__ void k_interp(const float* __restrict__ h2W, const float* __restrict__ h2b,
                         float* __restrict__ out) {
    int row  = blockIdx.x;
    int wid  = threadIdx.x >> 5;
    int lane = threadIdx.x & 31;
    const float* hrow = &g_H[(size_t)row * (3 * D_) + wid * D_];
    const float* w    = &h2W[wid * D_];
    float s = 0.f;
    for (int e = lane; e < D_; e += 32) s += hrow[e] * w[e];
#pragma unroll
    for (int o = 16; o; o >>= 1) s += __shfl_xor_sync(0xffffffffu, s, o);
    if (lane == 0) out[OFF_INTERP + wid * BN_ + row] = s + h2b[wid];
}

// ---------------- launch ----------------
extern "C" void kernel_launch(void* const* d_in, const int* in_sizes, int n_in,
                              void* d_out, int out_size) {
    const int*   ids  = (const int*)  d_in[0];
    const float* pos  = (const float*)d_in[1];
    const float* symt = (const float*)d_in[2];
    const float* layt = (const float*)d_in[3];
    const float* relW = (const float*)d_in[4];
    const float* relb = (const float*)d_in[5];
    const float* h1W  = (const float*)d_in[6];
    const float* h1b  = (const float*)d_in[7];
    const float* h2W  = (const float*)d_in[8];
    const float* h2b  = (const float*)d_in[9];
    const float* outW = (const float*)d_in[10];
    const float* outb = (const float*)d_in[11];
    float* out = (float*)d_out;

    float *pA, *pW, *pWc, *pH, *pS0;
    cudaGetSymbolAddress((void**)&pA,  g_A);
    cudaGetSymbolAddress((void**)&pW,  g_Wfull);
    cudaGetSymbolAddress((void**)&pWc, g_Wcat);
    cudaGetSymbolAddress((void**)&pH,  g_H);
    cudaGetSymbolAddress((void**)&pS0, g_S0);

    cudaFuncSetAttribute(mgemm2<0>, cudaFuncAttributeMaxDynamicSharedMemorySize, SMEM_BYTES);
    cudaFuncSetAttribute(mgemm2<1>, cudaFuncAttributeMaxDynamicSharedMemorySize, SMEM_BYTES);

    // order chosen so ncu's fixed capture slot (#4) lands on k_band
    k_sort  <<<B_, N_>>>(pos);
    k_embed <<<BN_, D_>>>(ids, symt, layt);
    k_prefix<<<B_ * 8, 256>>>();
    k_band  <<<B_ * 64, 256>>>(pos);
    k_wfull <<<(KA_ * D_ + 255) / 256, 256>>>(relW, relb);
    k_wcat  <<<(D_ * 4 * D_) / 256, 256>>>(h1W, h1b, outW, outb);

    float* d_sym = out + OFF_SYM;
    // grammar: symbols = S0 + A @ Wfull
    mgemm2<0><<<dim3(D_ / 64, BN_ / 128), 256, SMEM_BYTES>>>(
        pA, KA_, pW, D_, KA_, pS0, d_sym, nullptr);
    // fused heads (gelu -> g_H) + output projection (-> out)
    mgemm2<1><<<dim3(1024 / 64, BN_ / 128), 256, SMEM_BYTES>>>(
        d_sym, D_, pWc, 1024, D_, nullptr, pH, out);

    k_interp<<<BN_, 96>>>(h2W, h2b, out);
}

// round 10
// speedup vs baseline: 1.8554x; 1.1889x over previous
#include <cuda_runtime.h>
#include <math.h>
#include <stdint.h>

// Problem constants
#define B_   8
#define N_   512
#define D_   256
#define R_   6
#define BN_  (B_*N_)          // 4096 rows
#define KA_  1568             // 6*256 rel cols + 6 count cols + pad

// Output layout in d_out (floats)
#define OFF_INTERP 1048576
#define OFF_SYM    (1048576 + 3*4096)

// ---------------- scratch ----------------
__device__ float    g_S0[BN_ * D_];
__device__ float    g_A[BN_ * KA_];
__device__ float    g_Wfull[KA_ * D_];
__device__ float    g_Wcat[D_ * 4 * D_];    // [k][1024]: 3 head W's + outW
__device__ float    g_bcat[4 * D_];
__device__ float    g_H[BN_ * 3 * D_];
__device__ float    g_P[B_ * (N_ + 1) * D_];
__device__ int      g_sidx[B_ * N_];
__device__ int      g_k0o[B_ * N_];         // band bounds per ORIGINAL index
__device__ int      g_k1o[B_ * N_];
__device__ uint32_t g_code32[BN_ * (N_/4)]; // relation code byte per (b,j,m), 4 packed

// ---------------- small kernels ----------------
__global__ void k_embed(const int* __restrict__ ids,
                        const float* __restrict__ symt,
                        const float* __restrict__ layt) {
    int row = blockIdx.x, t = threadIdx.x;
    int id  = ids[row];
    g_S0[row * D_ + t] = symt[id * D_ + t] + layt[id * D_ + t];
}

// relation code per (j, m): dx = x[j]-x[m], dy = y[j]-y[m] (target minus source)
__device__ __forceinline__ unsigned rel_code(float dx, float dy, bool self) {
    if (self)                    return 255u;
    if (dy > 0.5f)               return 0u;
    if (dy < -0.5f)              return 1u;
    if (dx < -0.5f)              return 2u;
    if (dx > 0.5f)               return 3u;
    if (fabsf(dx) < 0.3f && fabsf(dy) < 0.3f) return 4u;
    return 5u;
}

// grid (16 jtiles, 8 b), 256 thr: write packed code matrix
__global__ void k_code(const float* __restrict__ pos) {
    __shared__ float xm[N_], ym[N_];
    int b  = blockIdx.y;
    int j0 = blockIdx.x * 32;
    int t  = threadIdx.x;
    for (int i = t; i < N_; i += 256) {
        xm[i] = pos[(b * N_ + i) * 2 + 0];
        ym[i] = pos[(b * N_ + i) * 2 + 1];
    }
    __syncthreads();
    for (int idx = t; idx < 32 * 128; idx += 256) {
        int jl = idx >> 7;          // 0..31
        int mg = idx & 127;         // m-group of 4
        int j  = j0 + jl;
        float xj = xm[j], yj = ym[j];
        uint32_t w = 0;
#pragma unroll
        for (int u = 0; u < 4; u++) {
            int m = mg * 4 + u;
            unsigned c = rel_code(xj - xm[m], yj - ym[m], m == j);
            w |= c << (u * 8);
        }
        g_code32[(size_t)(b * N_ + j) * 128 + mg] = w;
    }
}

__global__ void k_sort(const float* __restrict__ pos) {
    __shared__ float key[N_];
    __shared__ int   val[N_];
    int b = blockIdx.x, t = threadIdx.x;
    key[t] = pos[(b * N_ + t) * 2 + 1];
    val[t] = t;
    __syncthreads();
    for (int size = 2; size <= N_; size <<= 1) {
        for (int stride = size >> 1; stride > 0; stride >>= 1) {
            int j = t ^ stride;
            if (j > t) {
                bool up = ((t & size) == 0);
                float kt = key[t], kj = key[j];
                if ((kt > kj) == up) {
                    key[t] = kj; key[j] = kt;
                    int vt = val[t]; val[t] = val[j]; val[j] = vt;
                }
            }
            __syncthreads();
        }
    }
    g_sidx[b * N_ + t] = val[t];
    float y  = key[t];
    float v0 = y - 0.5f, v1 = y + 0.5f;
    int lo = 0, hi = N_;
    while (lo < hi) { int m = (lo + hi) >> 1; if (key[m] <  v0) lo = m + 1; else hi = m; }
    int k0 = lo;
    lo = 0; hi = N_;
    while (lo < hi) { int m = (lo + hi) >> 1; if (key[m] <= v1) lo = m + 1; else hi = m; }
    int orig = val[t];
    g_k0o[b * N_ + orig] = k0;
    g_k1o[b * N_ + orig] = lo;
}

// segmented parallel prefix: grid = B*8, block = 256
__global__ void k_prefix() {
    __shared__ float ssum[8][32];
    int b   = blockIdx.x >> 3;
    int g   = blockIdx.x & 7;
    int ch  = (threadIdx.x & 31) + g * 32;
    int seg = threadIdx.x >> 5;
    const int* si = &g_sidx[b * N_];
    int m0 = seg * 64;
    float s = 0.f;
#pragma unroll 4
    for (int m = 0; m < 64; m++)
        s += g_S0[(b * N_ + si[m0 + m]) * D_ + ch];
    ssum[seg][threadIdx.x & 31] = s;
    __syncthreads();
    float run = 0.f;
    for (int q = 0; q < seg; q++) run += ssum[q][threadIdx.x & 31];
    float* Pb = &g_P[(size_t)(b * (N_ + 1)) * D_ + ch];
#pragma unroll 4
    for (int m = 0; m < 64; m++) {
        Pb[(size_t)(m0 + m) * D_] = run;
        run += g_S0[(b * N_ + si[m0 + m]) * D_ + ch];
    }
    if (seg == 7) Pb[(size_t)N_ * D_] = run;
}

// merged weight-prep: Wfull (grammar) + Wcat/bcat (heads+out)
__global__ void k_weights(const float* __restrict__ relW, const float* __restrict__ relb,
                          const float* __restrict__ h1W, const float* __restrict__ h1b,
                          const float* __restrict__ outW, const float* __restrict__ outb) {
    const int W1 = KA_ * D_;          // 401408
    const int W2 = W1 + 1024 * D_;    // +262144
    int idx = blockIdx.x * 256 + threadIdx.x;
    if (idx < W1) {
        int row = idx / D_, e = idx % D_;
        float v;
        if (row < R_ * D_)            v = relW[idx];
        else if (row < R_ * D_ + R_)  v = relb[(row - R_ * D_) * D_ + e];
        else                          v = 0.f;
        g_Wfull[idx] = v;
    } else if (idx < W2) {
        int i = idx - W1;
        int k = i >> 10, n = i & 1023;
        g_Wcat[i] = (n < 768) ? h1W[((n >> 8) * D_ + k) * D_ + (n & 255)]
                              : outW[k * D_ + (n - 768)];
    } else if (idx < W2 + 1024) {
        int i = idx - W2;
        g_bcat[i] = (i < 768) ? h1b[(i >> 8) * D_ + (i & 255)] : outb[i - 768];
    }
}

// ---------------- tf32 helpers ----------------
__device__ __forceinline__ uint32_t f2tf32(float x) {
    uint32_t r;
    asm("cvt.rna.tf32.f32 %0, %1;" : "=r"(r) : "f"(x));
    return r;
}

__device__ __forceinline__ void mma_tf32(float* c, uint32_t a0, uint32_t a1,
                                         uint32_t a2, uint32_t a3,
                                         uint32_t b0, uint32_t b1) {
    asm volatile(
        "mma.sync.aligned.m16n8k8.row.col.f32.tf32.tf32.f32 "
        "{%0,%1,%2,%3}, {%4,%5,%6,%7}, {%8,%9}, {%0,%1,%2,%3};"
        : "+f"(c[0]), "+f"(c[1]), "+f"(c[2]), "+f"(c[3])
        : "r"(a0), "r"(a1), "r"(a2), "r"(a3), "r"(b0), "r"(b1));
}

// ---------------- masked band GEMM: A_r = Mask_r @ S0, r=2,3,4 ----------------
// grid (4 ch-tiles, 8 j-tiles, 8 b), 256 thr (8 warps: 4 m-slabs x 2 n-slabs)
// BM=64 (j), BN=64 (ch), K=512 (m) in chunks of 32. Masks exact in tf32 ->
// 2-pass (S hi + S lo) reproduces fp32 accumulation.
__global__ void __launch_bounds__(256) k_mgband() {
    __shared__ uint32_t      BsH[64 * 36], BsL[64 * 36];
    __shared__ unsigned char Cs[64 * 40];

    int b   = blockIdx.z;
    int j0  = blockIdx.y * 64;
    int ch0 = blockIdx.x * 64;
    int t    = threadIdx.x;
    int warp = t >> 5, lane = t & 31;
    int wm = warp >> 1;              // 0..3 -> 16-row slab
    int wn = warp & 1;               // 0..1 -> 32-col slab
    int qr = lane >> 2, qc = lane & 3;

    float acc[3][4][4];
#pragma unroll
    for (int r = 0; r < 3; r++)
#pragma unroll
        for (int nt = 0; nt < 4; nt++)
#pragma unroll
            for (int f = 0; f < 4; f++) acc[r][nt][f] = 0.f;

    const uint32_t ONE = 0x3F800000u;

    for (int kt = 0; kt < N_; kt += 32) {
        // stage code chunk [64 j x 32 m] (padded row stride 40B)
#pragma unroll
        for (int l = 0; l < 2; l++) {
            int w  = t + l * 256;       // 0..511
            int j  = w >> 3, kw = w & 7;
            uint32_t cw = g_code32[(size_t)(b * N_ + j0 + j) * 128 + (kt >> 2) + kw];
            *(uint32_t*)&Cs[j * 40 + kw * 4] = cw;
        }
        // stage B chunk: S0[m, ch] hi/lo as [n][k] stride 36
#pragma unroll
        for (int l = 0; l < 8; l++) {
            int id = t + l * 256;
            int k  = id >> 6, n = id & 63;
            float v = g_S0[(size_t)(b * N_ + kt + k) * D_ + ch0 + n];
            uint32_t h = f2tf32(v);
            BsH[n * 36 + k] = h;
            BsL[n * 36 + k] = f2tf32(v - __uint_as_float(h));
        }
        __syncthreads();

#pragma unroll
        for (int ks = 0; ks < 32; ks += 8) {
            int k0 = ks + qc;
            int rb = wm * 16 + qr;
            unsigned c00 = Cs[rb * 40 + k0];
            unsigned c10 = Cs[(rb + 8) * 40 + k0];
            unsigned c01 = Cs[rb * 40 + k0 + 4];
            unsigned c11 = Cs[(rb + 8) * 40 + k0 + 4];
            uint32_t bh[8], bl[8];
#pragma unroll
            for (int nt = 0; nt < 4; nt++) {
                int nb = wn * 32 + nt * 8 + qr;
                bh[nt*2+0] = BsH[nb * 36 + k0];
                bh[nt*2+1] = BsH[nb * 36 + k0 + 4];
                bl[nt*2+0] = BsL[nb * 36 + k0];
                bl[nt*2+1] = BsL[nb * 36 + k0 + 4];
            }
#pragma unroll
            for (int r = 0; r < 3; r++) {
                unsigned cr = r + 2;
                uint32_t a0 = (c00 == cr) ? ONE : 0u;
                uint32_t a1 = (c10 == cr) ? ONE : 0u;
                uint32_t a2 = (c01 == cr) ? ONE : 0u;
                uint32_t a3 = (c11 == cr) ? ONE : 0u;
#pragma unroll
                for (int nt = 0; nt < 4; nt++) {
                    mma_tf32(acc[r][nt], a0, a1, a2, a3, bh[nt*2], bh[nt*2+1]);
                    mma_tf32(acc[r][nt], a0, a1, a2, a3, bl[nt*2], bl[nt*2+1]);
                }
            }
        }
        __syncthreads();
    }

    // write class sums into g_A cols [2..4]*256
#pragma unroll
    for (int r = 0; r < 3; r++)
#pragma unroll
        for (int f = 0; f < 4; f++) {
            int row = j0 + wm * 16 + qr + ((f >= 2) ? 8 : 0);
#pragma unroll
            for (int nt = 0; nt < 4; nt++) {
                int col = ch0 + wn * 32 + nt * 8 + qc * 2 + (f & 1);
                g_A[(size_t)(b * N_ + row) * KA_ + (2 + r) * D_ + col] = acc[r][nt][f];
            }
        }
}

// per-row epilogue: r0/r1 from prefix, r5 derived, count columns
__global__ void k_fix() {
    __shared__ int sc[3];
    int row = blockIdx.x;            // 0..4095
    int b   = row >> 9;
    int t   = threadIdx.x;           // 256 = channels
    if (t < 3) sc[t] = 0;
    __syncthreads();
    if (t < 128) {
        uint32_t cw = g_code32[(size_t)row * 128 + t];
        int n2 = __popc(__vcmpeq4(cw, 0x02020202u)) >> 3;
        int n3 = __popc(__vcmpeq4(cw, 0x03030303u)) >> 3;
        int n4 = __popc(__vcmpeq4(cw, 0x04040404u)) >> 3;
#pragma unroll
        for (int o = 16; o; o >>= 1) {
            n2 += __shfl_down_sync(0xffffffffu, n2, o);
            n3 += __shfl_down_sync(0xffffffffu, n3, o);
            n4 += __shfl_down_sync(0xffffffffu, n4, o);
        }
        if ((t & 31) == 0) {
            atomicAdd(&sc[0], n2);
            atomicAdd(&sc[1], n3);
            atomicAdd(&sc[2], n4);
        }
    }
    __syncthreads();
    int k0 = g_k0o[row], k1 = g_k1o[row];
    const float* Pb = &g_P[(size_t)(b * (N_ + 1)) * D_];
    float p0  = Pb[(size_t)k0 * D_ + t];
    float p1  = Pb[(size_t)k1 * D_ + t];
    float tot = Pb[(size_t)N_ * D_ + t];
    float sj  = g_S0[(size_t)row * D_ + t];
    float* Ar = &g_A[(size_t)row * KA_];
    float a2 = Ar[2 * D_ + t];
    float a3 = Ar[3 * D_ + t];
    float a4 = Ar[4 * D_ + t];
    Ar[0 * D_ + t] = p0;
    Ar[1 * D_ + t] = tot - p1;
    Ar[5 * D_ + t] = (p1 - p0 - sj) - a2 - a3 - a4;
    if (t < 6) {
        float cv;
        if (t == 0)      cv = (float)k0;
        else if (t == 1) cv = (float)(N_ - k1);
        else if (t == 5) cv = (float)((k1 - k0 - 1) - sc[0] - sc[1] - sc[2]);
        else             cv = (float)sc[t - 2];
        Ar[R_ * D_ + t] = cv;
    }
}

// ---------------- main GEMMs (tf32 3-pass, hi/lo pre-split) ----------------
#define SM_AH 0
#define SM_AL (128*36)
#define SM_BH (2*128*36)
#define SM_BL (2*128*36 + 64*36)
#define SMEM_WORDS (2*128*36 + 2*64*36)
#define SMEM_BYTES (SMEM_WORDS * 4)

// MODE 0: C = A@Bm + addp  (grammar; N=256)
// MODE 1: fused heads+out  (N=1024; cols<768: gelu -> C(ld 768); else -> C2(ld 256))
template<int MODE>
__global__ void __launch_bounds__(256) mgemm2(
        const float* __restrict__ A, int lda,
        const float* __restrict__ Bm, int ldb, int K,
        const float* __restrict__ addp,
        float* __restrict__ C, float* __restrict__ C2) {
    extern __shared__ uint32_t sm[];
    uint32_t* AsH = sm + SM_AH;
    uint32_t* AsL = sm + SM_AL;
    uint32_t* BsH = sm + SM_BH;
    uint32_t* BsL = sm + SM_BL;

    int t    = threadIdx.x;
    int warp = t >> 5, lane = t & 31;
    int wm   = warp >> 1;
    int wn   = warp & 1;
    int bm0  = blockIdx.y * 128;
    int bn0  = blockIdx.x * 64;
    int qr   = lane >> 2;
    int qc   = lane & 3;

    float acc[2][4][4];
#pragma unroll
    for (int mt = 0; mt < 2; mt++)
#pragma unroll
        for (int nt = 0; nt < 4; nt++)
#pragma unroll
            for (int f = 0; f < 4; f++) acc[mt][nt][f] = 0.f;

    for (int kt = 0; kt < K; kt += 32) {
#pragma unroll
        for (int l = 0; l < 4; l++) {
            int id  = t + l * 256;
            int row = id >> 3;
            int kq  = (id & 7) * 4;
            float4 v = *(const float4*)&A[(size_t)(bm0 + row) * lda + kt + kq];
            float fe[4] = {v.x, v.y, v.z, v.w};
#pragma unroll
            for (int jj = 0; jj < 4; jj++) {
                uint32_t h = f2tf32(fe[jj]);
                AsH[row * 36 + kq + jj] = h;
                AsL[row * 36 + kq + jj] = f2tf32(fe[jj] - __uint_as_float(h));
            }
        }
#pragma unroll
        for (int l = 0; l < 8; l++) {
            int id = t + l * 256;
            int k  = id >> 6;
            int n  = id & 63;
            float v = Bm[(size_t)(kt + k) * ldb + bn0 + n];
            uint32_t h = f2tf32(v);
            BsH[n * 36 + k] = h;
            BsL[n * 36 + k] = f2tf32(v - __uint_as_float(h));
        }
        __syncthreads();

#pragma unroll
        for (int ks = 0; ks < 32; ks += 8) {
            int k0 = ks + qc;
            uint32_t ahi[8], alo[8];
#pragma unroll
            for (int mt = 0; mt < 2; mt++) {
                int rb = wm * 32 + mt * 16 + qr;
                ahi[mt*4+0] = AsH[rb * 36 + k0];
                ahi[mt*4+1] = AsH[(rb + 8) * 36 + k0];
                ahi[mt*4+2] = AsH[rb * 36 + k0 + 4];
                ahi[mt*4+3] = AsH[(rb + 8) * 36 + k0 + 4];
                alo[mt*4+0] = AsL[rb * 36 + k0];
                alo[mt*4+1] = AsL[(rb + 8) * 36 + k0];
                alo[mt*4+2] = AsL[rb * 36 + k0 + 4];
                alo[mt*4+3] = AsL[(rb + 8) * 36 + k0 + 4];
            }
            uint32_t bhi[8], blo[8];
#pragma unroll
            for (int nt = 0; nt < 4; nt++) {
                int nb = wn * 32 + nt * 8 + qr;
                bhi[nt*2+0] = BsH[nb * 36 + k0];
                bhi[nt*2+1] = BsH[nb * 36 + k0 + 4];
                blo[nt*2+0] = BsL[nb * 36 + k0];
                blo[nt*2+1] = BsL[nb * 36 + k0 + 4];
            }
#pragma unroll
            for (int mt = 0; mt < 2; mt++)
#pragma unroll
                for (int nt = 0; nt < 4; nt++) {
                    float* c = acc[mt][nt];
                    mma_tf32(c, ahi[mt*4], ahi[mt*4+1], ahi[mt*4+2], ahi[mt*4+3],
                             bhi[nt*2], bhi[nt*2+1]);
                    mma_tf32(c, alo[mt*4], alo[mt*4+1], alo[mt*4+2], alo[mt*4+3],
                             bhi[nt*2], bhi[nt*2+1]);
                    mma_tf32(c, ahi[mt*4], ahi[mt*4+1], ahi[mt*4+2], ahi[mt*4+3],
                             blo[nt*2], blo[nt*2+1]);
                }
        }
        __syncthreads();
    }

#pragma unroll
    for (int mt = 0; mt < 2; mt++) {
#pragma unroll
        for (int f = 0; f < 4; f++) {
            int row = bm0 + wm * 32 + mt * 16 + qr + ((f >= 2) ? 8 : 0);
#pragma unroll
            for (int nt = 0; nt < 4; nt++) {
                int col = bn0 + wn * 32 + nt * 8 + qc * 2 + (f & 1);
                float v = acc[mt][nt][f];
                if (MODE == 0) {
                    v += addp[(size_t)row * D_ + col];
                    C[(size_t)row * D_ + col] = v;
                } else {
                    v += g_bcat[col];
                    if (bn0 < 768) {
                        v = 0.5f * v * (1.f + erff(v * 0.70710678118654752440f));
                        C[(size_t)row * 768 + col] = v;
                    } else {
                        C2[(size_t)row * D_ + (col - 768)] = v;
                    }
                }
            }
        }
    }
}

__global__ void k_interp(const float* __restrict__ h2W, const float* __restrict__ h2b,
                         float* __restrict__ out) {
    int row  = blockIdx.x;
    int wid  = threadIdx.x >> 5;
    int lane = threadIdx.x & 31;
    const float* hrow = &g_H[(size_t)row * (3 * D_) + wid * D_];
    const float* w    = &h2W[wid * D_];
    float s = 0.f;
    for (int e = lane; e < D_; e += 32) s += hrow[e] * w[e];
#pragma unroll
    for (int o = 16; o; o >>= 1) s += __shfl_xor_sync(0xffffffffu, s, o);
    if (lane == 0) out[OFF_INTERP + wid * BN_ + row] = s + h2b[wid];
}

// ---------------- launch ----------------
extern "C" void kernel_launch(void* const* d_in, const int* in_sizes, int n_in,
                              void* d_out, int out_size) {
    const int*   ids  = (const int*)  d_in[0];
    const float* pos  = (const float*)d_in[1];
    const float* symt = (const float*)d_in[2];
    const float* layt = (const float*)d_in[3];
    const float* relW = (const float*)d_in[4];
    const float* relb = (const float*)d_in[5];
    const float* h1W  = (const float*)d_in[6];
    const float* h1b  = (const float*)d_in[7];
    const float* h2W  = (const float*)d_in[8];
    const float* h2b  = (const float*)d_in[9];
    const float* outW = (const float*)d_in[10];
    const float* outb = (const float*)d_in[11];
    float* out = (float*)d_out;

    float *pA, *pW, *pWc, *pH, *pS0;
    cudaGetSymbolAddress((void**)&pA,  g_A);
    cudaGetSymbolAddress((void**)&pW,  g_Wfull);
    cudaGetSymbolAddress((void**)&pWc, g_Wcat);
    cudaGetSymbolAddress((void**)&pH,  g_H);
    cudaGetSymbolAddress((void**)&pS0, g_S0);

    cudaFuncSetAttribute(mgemm2<0>, cudaFuncAttributeMaxDynamicSharedMemorySize, SMEM_BYTES);
    cudaFuncSetAttribute(mgemm2<1>, cudaFuncAttributeMaxDynamicSharedMemorySize, SMEM_BYTES);

    // order: k_mgband in launch slot #4 (ncu capture slot)
    k_code  <<<dim3(16, 8), 256>>>(pos);
    k_embed <<<BN_, D_>>>(ids, symt, layt);
    k_sort  <<<B_, N_>>>(pos);
    k_mgband<<<dim3(4, 8, 8), 256>>>();
    k_prefix<<<B_ * 8, 256>>>();
    {
        int total = KA_ * D_ + 1024 * D_ + 1024;
        k_weights<<<(total + 255) / 256, 256>>>(relW, relb, h1W, h1b, outW, outb);
    }
    k_fix   <<<BN_, 256>>>();

    float* d_sym = out + OFF_SYM;
    mgemm2<0><<<dim3(D_ / 64, BN_ / 128), 256, SMEM_BYTES>>>(
        pA, KA_, pW, D_, KA_, pS0, d_sym, nullptr);
    mgemm2<1><<<dim3(1024 / 64, BN_ / 128), 256, SMEM_BYTES>>>(
        d_sym, D_, pWc, 1024, D_, nullptr, pH, out);

    k_interp<<<BN_, 96>>>(h2W, h2b, out);
}

// round 11
// speedup vs baseline: 1.9467x; 1.0492x over previous
#include <cuda_runtime.h>
#include <math.h>
#include <stdint.h>

// Problem constants
#define B_   8
#define N_   512
#define D_   256
#define R_   6
#define BN_  (B_*N_)          // 4096 rows
#define KA_  1568             // 6*256 rel cols + 6 count cols + pad

// Output layout in d_out (floats)
#define OFF_INTERP 1048576
#define OFF_SYM    (1048576 + 3*4096)

// ---------------- scratch ----------------
__device__ float    g_S0[BN_ * D_];
__device__ float    g_A[BN_ * KA_];
__device__ float    g_Wfull[KA_ * D_];
__device__ float    g_Wcat[D_ * 4 * D_];    // [k][1024]: 3 head W's + outW
__device__ float    g_bcat[4 * D_];
__device__ float    g_H[BN_ * 3 * D_];
__device__ float    g_P[B_ * (N_ + 1) * D_];
__device__ int      g_sidx[B_ * N_];
__device__ int      g_k0o[B_ * N_];         // band bounds per ORIGINAL index
__device__ int      g_k1o[B_ * N_];
__device__ uint32_t g_code32[BN_ * (N_/4)]; // relation code byte per (b,j,m), 4 packed

// ---------------- small kernels ----------------
__global__ void k_embed(const int* __restrict__ ids,
                        const float* __restrict__ symt,
                        const float* __restrict__ layt) {
    int row = blockIdx.x, t = threadIdx.x;
    int id  = ids[row];
    g_S0[row * D_ + t] = symt[id * D_ + t] + layt[id * D_ + t];
}

__device__ __forceinline__ unsigned rel_code(float dx, float dy, bool self) {
    if (self)                    return 255u;
    if (dy > 0.5f)               return 0u;
    if (dy < -0.5f)              return 1u;
    if (dx < -0.5f)              return 2u;
    if (dx > 0.5f)               return 3u;
    if (fabsf(dx) < 0.3f && fabsf(dy) < 0.3f) return 4u;
    return 5u;
}

// grid (16 jtiles, 8 b), 256 thr: packed code matrix
__global__ void k_code(const float* __restrict__ pos) {
    __shared__ float xm[N_], ym[N_];
    int b  = blockIdx.y;
    int j0 = blockIdx.x * 32;
    int t  = threadIdx.x;
    for (int i = t; i < N_; i += 256) {
        xm[i] = pos[(b * N_ + i) * 2 + 0];
        ym[i] = pos[(b * N_ + i) * 2 + 1];
    }
    __syncthreads();
    for (int idx = t; idx < 32 * 128; idx += 256) {
        int jl = idx >> 7;
        int mg = idx & 127;
        int j  = j0 + jl;
        float xj = xm[j], yj = ym[j];
        uint32_t w = 0;
#pragma unroll
        for (int u = 0; u < 4; u++) {
            int m = mg * 4 + u;
            unsigned c = rel_code(xj - xm[m], yj - ym[m], m == j);
            w |= c << (u * 8);
        }
        g_code32[(size_t)(b * N_ + j) * 128 + mg] = w;
    }
}

__global__ void k_sort(const float* __restrict__ pos) {
    __shared__ float key[N_];
    __shared__ int   val[N_];
    int b = blockIdx.x, t = threadIdx.x;
    key[t] = pos[(b * N_ + t) * 2 + 1];
    val[t] = t;
    __syncthreads();
    for (int size = 2; size <= N_; size <<= 1) {
        for (int stride = size >> 1; stride > 0; stride >>= 1) {
            int j = t ^ stride;
            if (j > t) {
                bool up = ((t & size) == 0);
                float kt = key[t], kj = key[j];
                if ((kt > kj) == up) {
                    key[t] = kj; key[j] = kt;
                    int vt = val[t]; val[t] = val[j]; val[j] = vt;
                }
            }
            __syncthreads();
        }
    }
    g_sidx[b * N_ + t] = val[t];
    float y  = key[t];
    float v0 = y - 0.5f, v1 = y + 0.5f;
    int lo = 0, hi = N_;
    while (lo < hi) { int m = (lo + hi) >> 1; if (key[m] <  v0) lo = m + 1; else hi = m; }
    int k0 = lo;
    lo = 0; hi = N_;
    while (lo < hi) { int m = (lo + hi) >> 1; if (key[m] <= v1) lo = m + 1; else hi = m; }
    int orig = val[t];
    g_k0o[b * N_ + orig] = k0;
    g_k1o[b * N_ + orig] = lo;
}

// segmented parallel prefix: grid = B*8, block = 256
__global__ void k_prefix() {
    __shared__ float ssum[8][32];
    int b   = blockIdx.x >> 3;
    int g   = blockIdx.x & 7;
    int ch  = (threadIdx.x & 31) + g * 32;
    int seg = threadIdx.x >> 5;
    const int* si = &g_sidx[b * N_];
    int m0 = seg * 64;
    float s = 0.f;
#pragma unroll 4
    for (int m = 0; m < 64; m++)
        s += g_S0[(b * N_ + si[m0 + m]) * D_ + ch];
    ssum[seg][threadIdx.x & 31] = s;
    __syncthreads();
    float run = 0.f;
    for (int q = 0; q < seg; q++) run += ssum[q][threadIdx.x & 31];
    float* Pb = &g_P[(size_t)(b * (N_ + 1)) * D_ + ch];
#pragma unroll 4
    for (int m = 0; m < 64; m++) {
        Pb[(size_t)(m0 + m) * D_] = run;
        run += g_S0[(b * N_ + si[m0 + m]) * D_ + ch];
    }
    if (seg == 7) Pb[(size_t)N_ * D_] = run;
}

// merged weight-prep: Wfull (grammar) + Wcat/bcat (heads+out)
__global__ void k_weights(const float* __restrict__ relW, const float* __restrict__ relb,
                          const float* __restrict__ h1W, const float* __restrict__ h1b,
                          const float* __restrict__ outW, const float* __restrict__ outb) {
    const int W1 = KA_ * D_;
    const int W2 = W1 + 1024 * D_;
    int idx = blockIdx.x * 256 + threadIdx.x;
    if (idx < W1) {
        int row = idx / D_, e = idx % D_;
        float v;
        if (row < R_ * D_)            v = relW[idx];
        else if (row < R_ * D_ + R_)  v = relb[(row - R_ * D_) * D_ + e];
        else                          v = 0.f;
        g_Wfull[idx] = v;
    } else if (idx < W2) {
        int i = idx - W1;
        int k = i >> 10, n = i & 1023;
        g_Wcat[i] = (n < 768) ? h1W[((n >> 8) * D_ + k) * D_ + (n & 255)]
                              : outW[k * D_ + (n - 768)];
    } else if (idx < W2 + 1024) {
        int i = idx - W2;
        g_bcat[i] = (i < 768) ? h1b[(i >> 8) * D_ + (i & 255)] : outb[i - 768];
    }
}

// ---------------- tf32 helpers ----------------
__device__ __forceinline__ uint32_t f2tf32(float x) {
    uint32_t r;
    asm("cvt.rna.tf32.f32 %0, %1;" : "=r"(r) : "f"(x));
    return r;
}

__device__ __forceinline__ void mma_tf32(float* c, uint32_t a0, uint32_t a1,
                                         uint32_t a2, uint32_t a3,
                                         uint32_t b0, uint32_t b1) {
    asm volatile(
        "mma.sync.aligned.m16n8k8.row.col.f32.tf32.tf32.f32 "
        "{%0,%1,%2,%3}, {%4,%5,%6,%7}, {%8,%9}, {%0,%1,%2,%3};"
        : "+f"(c[0]), "+f"(c[1]), "+f"(c[2]), "+f"(c[3])
        : "r"(a0), "r"(a1), "r"(a2), "r"(a3), "r"(b0), "r"(b1));
}

// ---------------- masked band GEMM + full A-row epilogue ----------------
// grid (4 ch-tiles, 8 j-tiles, 8 b), 256 thr (8 warps: 4 j-slabs x 2 ch-slabs)
// BM=64 (j), BN=64 (ch), K=512 (m). Single tf32 pass (masks exact; S_hi only).
// Epilogue writes all 6 relation segments + count columns (ch-tile 0).
__global__ void __launch_bounds__(256, 3) k_mgband() {
    __shared__ uint32_t      BsH[64 * 36];
    __shared__ unsigned char Cs[64 * 40];
    __shared__ int           cnt[64][4];
    __shared__ int           sk0[64], sk1[64];

    int b   = blockIdx.z;
    int j0  = blockIdx.y * 64;
    int ch0 = blockIdx.x * 64;
    int t    = threadIdx.x;
    int warp = t >> 5, lane = t & 31;
    int wm = warp >> 1;              // 0..3 -> 16-row j slab
    int wn = warp & 1;               // 0..1 -> 32-col ch slab
    int qr = lane >> 2, qc = lane & 3;
    bool count_blk = (blockIdx.x == 0);

    if (t < 64) {
        sk0[t] = g_k0o[b * N_ + j0 + t];
        sk1[t] = g_k1o[b * N_ + j0 + t];
        cnt[t][0] = 0; cnt[t][1] = 0; cnt[t][2] = 0;
    }
    __syncthreads();

    float acc[3][4][4];
#pragma unroll
    for (int r = 0; r < 3; r++)
#pragma unroll
        for (int nt = 0; nt < 4; nt++)
#pragma unroll
            for (int f = 0; f < 4; f++) acc[r][nt][f] = 0.f;

    const uint32_t ONE = 0x3F800000u;

    for (int kt = 0; kt < N_; kt += 32) {
        // stage codes [64 j x 32 m]; accumulate counts (ch-tile 0 only)
#pragma unroll
        for (int l = 0; l < 2; l++) {
            int w  = t + l * 256;
            int j  = w >> 3, kw = w & 7;
            uint32_t cw = g_code32[(size_t)(b * N_ + j0 + j) * 128 + (kt >> 2) + kw];
            *(uint32_t*)&Cs[j * 40 + kw * 4] = cw;
            if (count_blk) {
                int n2 = __popc(__vcmpeq4(cw, 0x02020202u)) >> 3;
                int n3 = __popc(__vcmpeq4(cw, 0x03030303u)) >> 3;
                int n4 = __popc(__vcmpeq4(cw, 0x04040404u)) >> 3;
                if (n2) atomicAdd(&cnt[j][0], n2);
                if (n3) atomicAdd(&cnt[j][1], n3);
                if (n4) atomicAdd(&cnt[j][2], n4);
            }
        }
        // stage S0 chunk (hi only) as [n][k], stride 36
#pragma unroll
        for (int l = 0; l < 8; l++) {
            int id = t + l * 256;
            int k  = id >> 6, n = id & 63;
            float v = g_S0[(size_t)(b * N_ + kt + k) * D_ + ch0 + n];
            BsH[n * 36 + k] = f2tf32(v);
        }
        __syncthreads();

#pragma unroll
        for (int ks = 0; ks < 32; ks += 8) {
            int k0 = ks + qc;
            int rb = wm * 16 + qr;
            unsigned c00 = Cs[rb * 40 + k0];
            unsigned c10 = Cs[(rb + 8) * 40 + k0];
            unsigned c01 = Cs[rb * 40 + k0 + 4];
            unsigned c11 = Cs[(rb + 8) * 40 + k0 + 4];
            uint32_t bh[8];
#pragma unroll
            for (int nt = 0; nt < 4; nt++) {
                int nb = wn * 32 + nt * 8 + qr;
                bh[nt*2+0] = BsH[nb * 36 + k0];
                bh[nt*2+1] = BsH[nb * 36 + k0 + 4];
            }
#pragma unroll
            for (int r = 0; r < 3; r++) {
                unsigned cr = r + 2;
                uint32_t a0 = (c00 == cr) ? ONE : 0u;
                uint32_t a1 = (c10 == cr) ? ONE : 0u;
                uint32_t a2 = (c01 == cr) ? ONE : 0u;
                uint32_t a3 = (c11 == cr) ? ONE : 0u;
#pragma unroll
                for (int nt = 0; nt < 4; nt++)
                    mma_tf32(acc[r][nt], a0, a1, a2, a3, bh[nt*2], bh[nt*2+1]);
            }
        }
        __syncthreads();
    }

    // epilogue: full A row segments for this (j,ch) tile
    const float* Pb = &g_P[(size_t)(b * (N_ + 1)) * D_];
#pragma unroll
    for (int f = 0; f < 4; f++) {
        int rl   = wm * 16 + qr + ((f >= 2) ? 8 : 0);
        int grow = b * N_ + j0 + rl;
        int k0r = sk0[rl], k1r = sk1[rl];
        float* Ar = &g_A[(size_t)grow * KA_];
#pragma unroll
        for (int nt = 0; nt < 4; nt++) {
            int col = ch0 + wn * 32 + nt * 8 + qc * 2 + (f & 1);
            float p0  = Pb[(size_t)k0r * D_ + col];
            float p1  = Pb[(size_t)k1r * D_ + col];
            float tot = Pb[(size_t)N_ * D_ + col];
            float sj  = g_S0[(size_t)grow * D_ + col];
            float a2v = acc[0][nt][f];
            float a3v = acc[1][nt][f];
            float a4v = acc[2][nt][f];
            Ar[0 * D_ + col] = p0;
            Ar[1 * D_ + col] = tot - p1;
            Ar[2 * D_ + col] = a2v;
            Ar[3 * D_ + col] = a3v;
            Ar[4 * D_ + col] = a4v;
            Ar[5 * D_ + col] = (p1 - p0 - sj) - a2v - a3v - a4v;
        }
    }
    if (count_blk) {
        __syncthreads();
        if (t < 64) {
            int k0r = sk0[t], k1r = sk1[t];
            int n2 = cnt[t][0], n3 = cnt[t][1], n4 = cnt[t][2];
            float* Ar = &g_A[(size_t)(b * N_ + j0 + t) * KA_ + R_ * D_];
#pragma unroll
            for (int c = 0; c < 32; c++) {
                float cv = 0.f;
                if (c == 0)      cv = (float)k0r;
                else if (c == 1) cv = (float)(N_ - k1r);
                else if (c == 2) cv = (float)n2;
                else if (c == 3) cv = (float)n3;
                else if (c == 4) cv = (float)n4;
                else if (c == 5) cv = (float)((k1r - k0r - 1) - n2 - n3 - n4);
                Ar[c] = cv;
            }
        }
    }
}

// ---------------- main GEMMs (tf32 3-pass, hi/lo pre-split) ----------------
// MODE 0: C = A@Bm + addp  (grammar)
// MODE 1: fused heads+out  (cols<768: gelu -> C(ld 768); else -> C2(ld 256))
// BM=128, BN=BNt, 256 thr (8 warps: 4m x 2n), K%32==0.
template<int MODE, int BNt>
__global__ void __launch_bounds__(256) mgemm2(
        const float* __restrict__ A, int lda,
        const float* __restrict__ Bm, int ldb, int K,
        const float* __restrict__ addp,
        float* __restrict__ C, float* __restrict__ C2) {
    constexpr int HALF = BNt / 2;
    constexpr int NT   = HALF / 8;
    extern __shared__ uint32_t sm[];
    uint32_t* AsH = sm;
    uint32_t* AsL = sm + 128 * 36;
    uint32_t* BsH = sm + 2 * 128 * 36;
    uint32_t* BsL = BsH + BNt * 36;

    int t    = threadIdx.x;
    int warp = t >> 5, lane = t & 31;
    int wm   = warp >> 1;
    int wn   = warp & 1;
    int bm0  = blockIdx.y * 128;
    int bn0  = blockIdx.x * BNt;
    int qr   = lane >> 2;
    int qc   = lane & 3;

    float acc[2][NT][4];
#pragma unroll
    for (int mt = 0; mt < 2; mt++)
#pragma unroll
        for (int nt = 0; nt < NT; nt++)
#pragma unroll
            for (int f = 0; f < 4; f++) acc[mt][nt][f] = 0.f;

    for (int kt = 0; kt < K; kt += 32) {
#pragma unroll
        for (int l = 0; l < 4; l++) {
            int id  = t + l * 256;
            int row = id >> 3;
            int kq  = (id & 7) * 4;
            float4 v = *(const float4*)&A[(size_t)(bm0 + row) * lda + kt + kq];
            float fe[4] = {v.x, v.y, v.z, v.w};
#pragma unroll
            for (int jj = 0; jj < 4; jj++) {
                uint32_t h = f2tf32(fe[jj]);
                AsH[row * 36 + kq + jj] = h;
                AsL[row * 36 + kq + jj] = f2tf32(fe[jj] - __uint_as_float(h));
            }
        }
#pragma unroll
        for (int l = 0; l < (BNt * 32) / 256; l++) {
            int id = t + l * 256;
            int k  = id / BNt;
            int n  = id % BNt;
            float v = Bm[(size_t)(kt + k) * ldb + bn0 + n];
            uint32_t h = f2tf32(v);
            BsH[n * 36 + k] = h;
            BsL[n * 36 + k] = f2tf32(v - __uint_as_float(h));
        }
        __syncthreads();

#pragma unroll
        for (int ks = 0; ks < 32; ks += 8) {
            int k0 = ks + qc;
            uint32_t ahi[8], alo[8];
#pragma unroll
            for (int mt = 0; mt < 2; mt++) {
                int rb = wm * 32 + mt * 16 + qr;
                ahi[mt*4+0] = AsH[rb * 36 + k0];
                ahi[mt*4+1] = AsH[(rb + 8) * 36 + k0];
                ahi[mt*4+2] = AsH[rb * 36 + k0 + 4];
                ahi[mt*4+3] = AsH[(rb + 8) * 36 + k0 + 4];
                alo[mt*4+0] = AsL[rb * 36 + k0];
                alo[mt*4+1] = AsL[(rb + 8) * 36 + k0];
                alo[mt*4+2] = AsL[rb * 36 + k0 + 4];
                alo[mt*4+3] = AsL[(rb + 8) * 36 + k0 + 4];
            }
            uint32_t bhi[2*NT], blo[2*NT];
#pragma unroll
            for (int nt = 0; nt < NT; nt++) {
                int nb = wn * HALF + nt * 8 + qr;
                bhi[nt*2+0] = BsH[nb * 36 + k0];
                bhi[nt*2+1] = BsH[nb * 36 + k0 + 4];
                blo[nt*2+0] = BsL[nb * 36 + k0];
                blo[nt*2+1] = BsL[nb * 36 + k0 + 4];
            }
#pragma unroll
            for (int mt = 0; mt < 2; mt++)
#pragma unroll
                for (int nt = 0; nt < NT; nt++) {
                    float* c = acc[mt][nt];
                    mma_tf32(c, ahi[mt*4], ahi[mt*4+1], ahi[mt*4+2], ahi[mt*4+3],
                             bhi[nt*2], bhi[nt*2+1]);
                    mma_tf32(c, alo[mt*4], alo[mt*4+1], alo[mt*4+2], alo[mt*4+3],
                             bhi[nt*2], bhi[nt*2+1]);
                    mma_tf32(c, ahi[mt*4], ahi[mt*4+1], ahi[mt*4+2], ahi[mt*4+3],
                             blo[nt*2], blo[nt*2+1]);
                }
        }
        __syncthreads();
    }

#pragma unroll
    for (int mt = 0; mt < 2; mt++) {
#pragma unroll
        for (int f = 0; f < 4; f++) {
            int row = bm0 + wm * 32 + mt * 16 + qr + ((f >= 2) ? 8 : 0);
#pragma unroll
            for (int nt = 0; nt < NT; nt++) {
                int col = bn0 + wn * HALF + nt * 8 + qc * 2 + (f & 1);
                float v = acc[mt][nt][f];
                if (MODE == 0) {
                    v += addp[(size_t)row * D_ + col];
                    C[(size_t)row * D_ + col] = v;
                } else {
                    v += g_bcat[col];
                    if (bn0 < 768) {
                        v = 0.5f * v * (1.f + erff(v * 0.70710678118654752440f));
                        C[(size_t)row * 768 + col] = v;
                    } else {
                        C2[(size_t)row * D_ + (col - 768)] = v;
                    }
                }
            }
        }
    }
}

__global__ void k_interp(const float* __restrict__ h2W, const float* __restrict__ h2b,
                         float* __restrict__ out) {
    int row  = blockIdx.x;
    int wid  = threadIdx.x >> 5;
    int lane = threadIdx.x & 31;
    const float* hrow = &g_H[(size_t)row * (3 * D_) + wid * D_];
    const float* w    = &h2W[wid * D_];
    float s = 0.f;
    for (int e = lane; e < D_; e += 32) s += hrow[e] * w[e];
#pragma unroll
    for (int o = 16; o; o >>= 1) s += __shfl_xor_sync(0xffffffffu, s, o);
    if (lane == 0) out[OFF_INTERP + wid * BN_ + row] = s + h2b[wid];
}

// ---------------- launch ----------------
#define SMB(BNt) ((2*128*36 + 2*(BNt)*36) * 4)

extern "C" void kernel_launch(void* const* d_in, const int* in_sizes, int n_in,
                              void* d_out, int out_size) {
    const int*   ids  = (const int*)  d_in[0];
    const float* pos  = (const float*)d_in[1];
    const float* symt = (const float*)d_in[2];
    const float* layt = (const float*)d_in[3];
    const float* relW = (const float*)d_in[4];
    const float* relb = (const float*)d_in[5];
    const float* h1W  = (const float*)d_in[6];
    const float* h1b  = (const float*)d_in[7];
    const float* h2W  = (const float*)d_in[8];
    const float* h2b  = (const float*)d_in[9];
    const float* outW = (const float*)d_in[10];
    const float* outb = (const float*)d_in[11];
    float* out = (float*)d_out;

    float *pA, *pW, *pWc, *pH, *pS0;
    cudaGetSymbolAddress((void**)&pA,  g_A);
    cudaGetSymbolAddress((void**)&pW,  g_Wfull);
    cudaGetSymbolAddress((void**)&pWc, g_Wcat);
    cudaGetSymbolAddress((void**)&pH,  g_H);
    cudaGetSymbolAddress((void**)&pS0, g_S0);

    cudaFuncSetAttribute((const void*)mgemm2<0,32>,
                         cudaFuncAttributeMaxDynamicSharedMemorySize, SMB(32));
    cudaFuncSetAttribute((const void*)mgemm2<1,64>,
                         cudaFuncAttributeMaxDynamicSharedMemorySize, SMB(64));

    k_code  <<<dim3(16, 8), 256>>>(pos);
    k_embed <<<BN_, D_>>>(ids, symt, layt);
    k_sort  <<<B_, N_>>>(pos);
    k_prefix<<<B_ * 8, 256>>>();
    {
        int total = KA_ * D_ + 1024 * D_ + 1024;
        k_weights<<<(total + 255) / 256, 256>>>(relW, relb, h1W, h1b, outW, outb);
    }
    k_mgband<<<dim3(4, 8, 8), 256>>>();

    float* d_sym = out + OFF_SYM;
    // grammar: symbols = S0 + A @ Wfull  (BN=32 -> 256 blocks)
    mgemm2<0,32><<<dim3(D_ / 32, BN_ / 128), 256, SMB(32)>>>(
        pA, KA_, pW, D_, KA_, pS0, d_sym, nullptr);
    // fused heads (gelu -> g_H) + output projection (-> out)
    mgemm2<1,64><<<dim3(1024 / 64, BN_ / 128), 256, SMB(64)>>>(
        d_sym, D_, pWc, 1024, D_, nullptr, pH, out);

    k_interp<<<BN_, 96>>>(h2W, h2b, out);
}